// round 1
// baseline (speedup 1.0000x reference)
#include <cuda_runtime.h>

// HEALPixPadding: [96,256,64,64] fp32, p=2 -> [96,256,68,68]
// Faces: nf = b*12 + f; f 0-3 north, 4-7 equatorial, 8-11 south.

constexpr int NPLANES   = 96 * 256;          // (nf, ch) planes = 24576
constexpr int PLANE_IN  = 64 * 64;           // 4096
constexpr int PLANE_OUT = 68 * 68;           // 4624
constexpr unsigned NB_INT = 196608;          // NPLANES*64*32 float2 / 256
constexpr int N_BORDER  = NPLANES * 528;     // 12,976,128 border elements
constexpr unsigned NB_BORDER = (unsigned)(N_BORDER / 256);  // 50688 (exact)

__global__ void __launch_bounds__(256) hpx_pad_kernel(const float* __restrict__ in,
                                                      float* __restrict__ out)
{
    unsigned bid = blockIdx.x;

    if (bid < NB_INT) {
        // ---------------- interior copy: out[...,2:66,2:66] = in ----------------
        unsigned t     = bid * 256u + threadIdx.x;    // float2 element index
        unsigned col2  = t & 31u;                     // 0..31 (pairs of floats)
        unsigned row   = (t >> 5) & 63u;              // 0..63
        unsigned plane = t >> 11;                     // 0..24575
        float2 v = reinterpret_cast<const float2*>(in)[plane * 2048u + row * 32u + col2];
        // float offset = plane*4624 + (row+2)*68 + 2 + 2*col2  (even)
        unsigned o2 = plane * 2312u + (row + 2u) * 34u + 1u + col2;
        reinterpret_cast<float2*>(out)[o2] = v;
        return;
    }

    // ---------------- border gather ----------------
    unsigned e = (bid - NB_INT) * 256u + threadIdx.x;
    if (e >= (unsigned)N_BORDER) return;

    unsigned plane = e / 528u;
    unsigned k     = e - plane * 528u;
    unsigned nf    = plane >> 8;          // /256
    unsigned ch    = plane & 255u;
    unsigned bb    = nf / 12u;
    int      f     = (int)(nf - bb * 12u);

    // k -> (r,c) over border positions of the 68x68 tile
    int r, c;
    if (k < 136u) {                       // top 2 rows
        r = (int)(k / 68u); c = (int)(k - (unsigned)r * 68u);
    } else if (k < 272u) {                // bottom 2 rows
        unsigned m = k - 136u;
        int mr = (int)(m / 68u);
        r = 66 + mr; c = (int)(m - (unsigned)mr * 68u);
    } else {                              // side columns, rows 2..65
        unsigned m = k - 272u;
        r = 2 + (int)(m >> 2);
        int q = (int)(m & 3u);
        c = (q < 2) ? q : q + 64;         // 0,1,66,67
    }

    int typ = f >> 2;        // 0=north 1=eq 2=south
    int n   = f & 3;

    // neighbor faces
    int ft, ftl, flf, fbl, fbo, fbr, frg, ftr;
    if (typ == 0) {
        ft  = (n + 1) & 3;  ftl = (n + 2) & 3;  flf = (n + 3) & 3;  fbl = flf;
        fbo = n + 4;        fbr = n + 8;        frg = ((n + 1) & 3) + 4;  ftr = ft;
    } else if (typ == 1) {
        ft  = n;            flf = (n + 3) & 3;  fbl = ((n + 3) & 3) + 4;
        fbo = ((n + 3) & 3) + 8;  frg = n + 8;  ftr = ((n + 1) & 3) + 4;
        ftl = -1; fbr = -1;  // synthesized corners
    } else {
        ft  = ((n + 1) & 3) + 4;  ftl = n;  flf = n + 4;
        fbl = ((n + 3) & 3) + 8;  fbo = fbl;
        fbr = ((n + 2) & 3) + 8;  frg = ((n + 1) & 3) + 8;  ftr = frg;
    }

    int rg_r = (r < 2) ? 0 : (r < 66 ? 1 : 2);
    int rg_c = (c < 2) ? 0 : (c < 66 ? 1 : 2);
    int reg  = rg_r * 3 + rg_c;

    int sf0 = 0, sr0 = 0, sc0 = 0;
    int sf1 = -1, sr1 = 0, sc1 = 0;

    switch (reg) {
    case 0:  // top-left
        if (typ == 0)      { sf0 = ftl; sr0 = 1 - r;   sc0 = 1 - c; }
        else if (typ == 2) { sf0 = ftl; sr0 = 62 + r;  sc0 = 62 + c; }
        else {             // eq: synthesized _tl(t, lft)
            if (c > r)      { sf0 = ft;  sr0 = 62 + r;     sc0 = c - r - 1; }
            else if (c < r) { sf0 = flf; sr0 = r - c - 1;  sc0 = 62 + c; }
            else            { sf0 = ft;  sr0 = 62 + r;  sc0 = 0;
                              sf1 = flf; sr1 = 0;       sc1 = 62 + r; }
        }
        break;
    case 1:  // top-mid
        if (typ == 0) { sf0 = ft; sr0 = c - 2;  sc0 = 1 - r; }
        else          { sf0 = ft; sr0 = 62 + r; sc0 = c - 2; }
        break;
    case 2:  // top-right (same for all types)
        sf0 = ftr; sr0 = 62 + r; sc0 = c - 66;
        break;
    case 3:  // mid-left
        if (typ == 0) { sf0 = flf; sr0 = 1 - c;  sc0 = r - 2; }
        else          { sf0 = flf; sr0 = r - 2;  sc0 = 62 + c; }
        break;
    case 5:  // mid-right
        if (typ == 2) { sf0 = frg; sr0 = 129 - c; sc0 = r - 2; }
        else          { sf0 = frg; sr0 = r - 2;   sc0 = c - 66; }
        break;
    case 6:  // bottom-left (same for all types)
        sf0 = fbl; sr0 = r - 66; sc0 = 62 + c;
        break;
    case 7:  // bottom-mid
        if (typ == 2) { sf0 = fbo; sr0 = c - 2;  sc0 = 129 - r; }
        else          { sf0 = fbo; sr0 = r - 66; sc0 = c - 2; }
        break;
    default: // case 8: bottom-right
        if (typ == 0)      { sf0 = fbr; sr0 = r - 66;  sc0 = c - 66; }
        else if (typ == 2) { sf0 = fbr; sr0 = 129 - r; sc0 = 129 - c; }
        else {             // eq: synthesized _br(b, rgt)
            int rr = r - 66, cc = c - 66;
            if (cc < rr)      { sf0 = fbo; sr0 = rr;            sc0 = 64 - rr + cc; }
            else if (cc > rr) { sf0 = frg; sr0 = 64 - cc + rr;  sc0 = cc; }
            else              { sf0 = fbo; sr0 = rr; sc0 = 63;
                                sf1 = frg; sr1 = 63; sc1 = rr; }
        }
        break;
    }

    unsigned srcBase = (bb * 12u) * 256u + ch;   // (b*12 + face)*256 + ch, face added below
    unsigned i0 = (srcBase + (unsigned)sf0 * 256u) * (unsigned)PLANE_IN
                + (unsigned)(sr0 * 64 + sc0);
    float v = __ldg(in + i0);
    if (sf1 >= 0) {
        unsigned i1 = (srcBase + (unsigned)sf1 * 256u) * (unsigned)PLANE_IN
                    + (unsigned)(sr1 * 64 + sc1);
        v = 0.5f * v + 0.5f * __ldg(in + i1);
    }
    out[plane * (unsigned)PLANE_OUT + (unsigned)(r * 68 + c)] = v;
}

extern "C" void kernel_launch(void* const* d_in, const int* in_sizes, int n_in,
                              void* d_out, int out_size)
{
    const float* in = (const float*)d_in[0];
    float* out = (float*)d_out;
    hpx_pad_kernel<<<NB_INT + NB_BORDER, 256>>>(in, out);
}